// round 12
// baseline (speedup 1.0000x reference)
#include <cuda_runtime.h>
#include <cuda_fp16.h>
#include <cstdint>

// CrossAttUnit fused — fp16-split (Ootomo) warp MMA, smem-free GEMM1.
// N=262144, H=256, D=64, L=64, B=4096. 1 segment/CTA, 256 threads, 4 CTAs/SM.
// GEMM1 operands loaded in MMA fragment layout directly from gmem (A split in
// regs; B pre-packed per-lane fragment image). Only GEMM2 uses smem (32 KB).

#define HDIM 256
#define SMEM_BYTES 32768u
// GEMM2 tile byte offsets in dynamic smem: ykhi 0, yklo 8192, yqhi 16384, yqlo 24576

// B fragment images: [chunk 0..7][mat 0..1][nhalf 0..1][u 0..3][lane 0..31][uint4]
__device__ __align__(16) unsigned char g_bh[65536];
__device__ __align__(16) unsigned char g_bl[65536];

__global__ void split_kq_kernel(const float* __restrict__ kmat,
                                const float* __restrict__ qmat) {
    int gid = blockIdx.x * 256 + threadIdx.x;        // 32768 = 2 x 256 x 64
    int m = gid >> 14, kglob = (gid >> 6) & 255, n = gid & 63;
    float x = m ? qmat[kglob * 64 + n] : kmat[kglob * 64 + n];
    __half hi = __float2half_rn(x);
    __half lo = __float2half_rn(x - __half2float(hi));
    int chunk = kglob >> 5, kk = kglob & 31, ks = kk >> 4, kr = kk & 15;
    int breg = kr >> 3, hpos = kr & 1, l2 = (kr >> 1) & 3;
    int nhalf = n >> 5, nn = n & 31, n8 = nn >> 3, lhi = nn & 7;
    int lane = lhi * 4 + l2;
    int regidx = ks * 8 + n8 * 2 + breg;
    int u = regidx >> 2, j = regidx & 3;
    uint32_t hoff = (uint32_t)((((chunk * 4 + m * 2 + nhalf) * 4 + u) * 32 + lane) * 8
                               + j * 2 + hpos);
    ((__half*)g_bh)[hoff] = hi;
    ((__half*)g_bl)[hoff] = lo;
}

__device__ __forceinline__ uint32_t smem_u32(const void* p) {
    uint32_t a;
    asm("{ .reg .u64 t; cvta.to.shared.u64 t, %1; cvt.u32.u64 %0, t; }" : "=r"(a) : "l"(p));
    return a;
}
__device__ __forceinline__ void ldsm4(uint32_t r[4], uint32_t addr) {
    asm volatile("ldmatrix.sync.aligned.m8n8.x4.shared.b16 {%0,%1,%2,%3}, [%4];"
                 : "=r"(r[0]), "=r"(r[1]), "=r"(r[2]), "=r"(r[3]) : "r"(addr));
}
__device__ __forceinline__ void mma16816(float c[4], const uint32_t a[4],
                                         uint32_t b0, uint32_t b1) {
    asm("mma.sync.aligned.m16n8k16.row.col.f32.f16.f16.f32 "
        "{%0,%1,%2,%3},{%4,%5,%6,%7},{%8,%9},{%0,%1,%2,%3};"
        : "+f"(c[0]), "+f"(c[1]), "+f"(c[2]), "+f"(c[3])
        : "r"(a[0]), "r"(a[1]), "r"(a[2]), "r"(a[3]), "r"(b0), "r"(b1));
}
__device__ __forceinline__ void split2(float x0, float x1, uint32_t& hi, uint32_t& lo) {
    __half h0 = __float2half_rn(x0), h1 = __float2half_rn(x1);
    __half l0 = __float2half_rn(x0 - __half2float(h0));
    __half l1 = __float2half_rn(x1 - __half2float(h1));
    __half2 H = __halves2half2(h0, h1), L = __halves2half2(l0, l1);
    hi = *(uint32_t*)&H;
    lo = *(uint32_t*)&L;
}

__global__ __launch_bounds__(256, 4)
void cross_att_r12(const float* __restrict__ yhat,
                   const float* __restrict__ y,
                   float* __restrict__ out) {
    extern __shared__ unsigned char smc[];
    const uint32_t sb = smem_u32(smc);
    const int tid = threadIdx.x, wid = tid >> 5, lane = tid & 31;
    __shared__ float rred[2][64];
    __shared__ float rsum[2][64];
    __shared__ float cpart[4][64];
    __shared__ float csum_inv[64];

    const long rowbase = (long)blockIdx.x * 64;
    const int mat = wid >> 2;                // 0: yk (y,k) ; 1: yq (yhat,q)
    const int w2 = wid & 3;
    const int mrow0 = (w2 & 1) * 32;
    const int ncol0 = (w2 >> 1) * 32;

    float cc[2][4][4];
    #pragma unroll
    for (int a = 0; a < 2; a++)
        #pragma unroll
        for (int b = 0; b < 4; b++)
            #pragma unroll
            for (int j = 0; j < 4; j++) cc[a][b][j] = 0.0f;

    // ---------------- GEMM1: fragment-direct, no smem, no barriers ----------------
    {
        const float* amat = mat ? yhat : y;
        const int g = lane >> 2, c2 = (lane & 3) * 2;
        const float* ap0 = amat + (rowbase + mrow0 + g) * HDIM + c2;
        const uint4* pbh = (const uint4*)g_bh + (uint32_t)((mat * 2 + (ncol0 >> 5)) * 128 + lane);
        const uint4* pbl = (const uint4*)g_bl + (uint32_t)((mat * 2 + (ncol0 >> 5)) * 128 + lane);

        #pragma unroll 1
        for (int c = 0; c < 8; c++) {
            #pragma unroll
            for (int ks = 0; ks < 2; ks++) {
                const int co = c * 32 + ks * 16;
                const uint4 BH0 = pbh[c * 512 + ks * 64];
                const uint4 BH1 = pbh[c * 512 + ks * 64 + 32];
                const uint4 BL0 = pbl[c * 512 + ks * 64];
                const uint4 BL1 = pbl[c * 512 + ks * 64 + 32];

                uint32_t ah[2][4], al[2][4];
                #pragma unroll
                for (int mt = 0; mt < 2; mt++) {
                    const float* r = ap0 + mt * (16 * HDIM) + co;
                    float2 f0 = *(const float2*)(r);
                    float2 f1 = *(const float2*)(r + 8 * HDIM);
                    float2 f2 = *(const float2*)(r + 8);
                    float2 f3 = *(const float2*)(r + 8 * HDIM + 8);
                    split2(f0.x, f0.y, ah[mt][0], al[mt][0]);
                    split2(f1.x, f1.y, ah[mt][1], al[mt][1]);
                    split2(f2.x, f2.y, ah[mt][2], al[mt][2]);
                    split2(f3.x, f3.y, ah[mt][3], al[mt][3]);
                }
                #pragma unroll
                for (int mt = 0; mt < 2; mt++) {
                    // per-accumulator order: hh, hl, lh (matches prior rounds)
                    mma16816(cc[mt][0], ah[mt], BH0.x, BH0.y);
                    mma16816(cc[mt][1], ah[mt], BH0.z, BH0.w);
                    mma16816(cc[mt][2], ah[mt], BH1.x, BH1.y);
                    mma16816(cc[mt][3], ah[mt], BH1.z, BH1.w);
                    mma16816(cc[mt][0], ah[mt], BL0.x, BL0.y);
                    mma16816(cc[mt][1], ah[mt], BL0.z, BL0.w);
                    mma16816(cc[mt][2], ah[mt], BL1.x, BL1.y);
                    mma16816(cc[mt][3], ah[mt], BL1.z, BL1.w);
                    mma16816(cc[mt][0], al[mt], BH0.x, BH0.y);
                    mma16816(cc[mt][1], al[mt], BH0.z, BH0.w);
                    mma16816(cc[mt][2], al[mt], BH1.x, BH1.y);
                    mma16816(cc[mt][3], al[mt], BH1.z, BH1.w);
                }
            }
        }
    }

    // ---------------- split yk/yq -> GEMM2 tiles (SW128, 64x128B) ----------------
    {
        const uint32_t HIb = mat ? 16384u : 0u;     // yq hi : yk hi
        const int rbase = mrow0 + (lane >> 2);
        const int cbase = ncol0 + (lane & 3) * 2;
        #pragma unroll
        for (int mt = 0; mt < 2; mt++) {
            #pragma unroll
            for (int nt = 0; nt < 4; nt++) {
                const int col = cbase + nt * 8;
                const uint32_t cpartb = (uint32_t)(((col >> 3) << 4) + (col & 7) * 2);
                #pragma unroll
                for (int h = 0; h < 2; h++) {
                    const int r = rbase + mt * 16 + h * 8;
                    const uint32_t off = (uint32_t)(r * 128) + (cpartb ^ (uint32_t)((r & 7) << 4));
                    uint32_t hi, lo;
                    split2(cc[mt][nt][2 * h], cc[mt][nt][2 * h + 1], hi, lo);
                    *(uint32_t*)(smc + HIb + off)         = hi;
                    *(uint32_t*)(smc + HIb + 8192u + off) = lo;
                }
            }
        }
    }
    __syncthreads();

    // ---------------- GEMM2 + register epilogue ----------------
    {
        const int rt = wid & 3, ch = wid >> 2;
        const int ct = ch * 32;
        float cm[4][4];
        #pragma unroll
        for (int n = 0; n < 4; n++)
            #pragma unroll
            for (int j = 0; j < 4; j++) cm[n][j] = 0.0f;

        const int rowG = rt * 16 + (lane & 15);
        const int g0 = lane >> 4;
        const uint32_t aBase = sb + (uint32_t)(rowG * 128 + ((g0 ^ (rowG & 7)) << 4));
        const int rowB0 = ct + (lane & 15), rowB1 = rowB0 + 16;
        const uint32_t bBase0 = sb + 16384u + (uint32_t)(rowB0 * 128 + ((g0 ^ (rowB0 & 7)) << 4));
        const uint32_t bBase1 = sb + 16384u + (uint32_t)(rowB1 * 128 + ((g0 ^ (rowB1 & 7)) << 4));

        #pragma unroll
        for (int ks = 0; ks < 4; ks++) {
            const uint32_t kx = (uint32_t)(ks * 32);
            uint32_t Ah[4], Al[4];
            ldsm4(Ah, aBase ^ kx);
            ldsm4(Al, (aBase + 8192u) ^ kx);
            #pragma unroll
            for (int nl = 0; nl < 2; nl++) {
                const uint32_t bB = nl ? bBase1 : bBase0;
                uint32_t Bh[4], Bl[4];
                ldsm4(Bh, bB ^ kx);
                ldsm4(Bl, (bB + 8192u) ^ kx);
                const int nb = 2 * nl;
                mma16816(cm[nb],     Ah, Bh[0], Bh[2]);
                mma16816(cm[nb + 1], Ah, Bh[1], Bh[3]);
                mma16816(cm[nb],     Ah, Bl[0], Bl[2]);
                mma16816(cm[nb + 1], Ah, Bl[1], Bl[3]);
                mma16816(cm[nb],     Al, Bh[0], Bh[2]);
                mma16816(cm[nb + 1], Al, Bh[1], Bh[3]);
            }
        }

        // ---- scale ----
        #pragma unroll
        for (int nt = 0; nt < 4; nt++)
            #pragma unroll
            for (int j = 0; j < 4; j++) cm[nt][j] *= 0.125f;

        const int r0 = rt * 16 + (lane >> 2);
        const int cb = (lane & 3) * 2;

        // ---- row max over warp's 32 cols, then cross-warp merge ----
        float m0 = fmaxf(fmaxf(cm[0][0], cm[0][1]), fmaxf(cm[1][0], cm[1][1]));
        m0 = fmaxf(m0, fmaxf(fmaxf(cm[2][0], cm[2][1]), fmaxf(cm[3][0], cm[3][1])));
        float m1 = fmaxf(fmaxf(cm[0][2], cm[0][3]), fmaxf(cm[1][2], cm[1][3]));
        m1 = fmaxf(m1, fmaxf(fmaxf(cm[2][2], cm[2][3]), fmaxf(cm[3][2], cm[3][3])));
        m0 = fmaxf(m0, __shfl_xor_sync(0xffffffffu, m0, 1));
        m0 = fmaxf(m0, __shfl_xor_sync(0xffffffffu, m0, 2));
        m1 = fmaxf(m1, __shfl_xor_sync(0xffffffffu, m1, 1));
        m1 = fmaxf(m1, __shfl_xor_sync(0xffffffffu, m1, 2));
        if ((lane & 3) == 0) { rred[ch][r0] = m0; rred[ch][r0 + 8] = m1; }
        __syncthreads();
        m0 = fmaxf(m0, rred[ch ^ 1][r0]);
        m1 = fmaxf(m1, rred[ch ^ 1][r0 + 8]);

        // ---- exp + row sums ----
        float s0 = 0.0f, s1 = 0.0f;
        #pragma unroll
        for (int nt = 0; nt < 4; nt++) {
            cm[nt][0] = __expf(cm[nt][0] - m0); s0 += cm[nt][0];
            cm[nt][1] = __expf(cm[nt][1] - m0); s0 += cm[nt][1];
            cm[nt][2] = __expf(cm[nt][2] - m1); s1 += cm[nt][2];
            cm[nt][3] = __expf(cm[nt][3] - m1); s1 += cm[nt][3];
        }
        s0 += __shfl_xor_sync(0xffffffffu, s0, 1);
        s0 += __shfl_xor_sync(0xffffffffu, s0, 2);
        s1 += __shfl_xor_sync(0xffffffffu, s1, 1);
        s1 += __shfl_xor_sync(0xffffffffu, s1, 2);
        if ((lane & 3) == 0) { rsum[ch][r0] = s0; rsum[ch][r0 + 8] = s1; }
        __syncthreads();
        s0 += rsum[ch ^ 1][r0];
        s1 += rsum[ch ^ 1][r0 + 8];
        const float inv0 = 1.0f / s0, inv1 = 1.0f / s1;
        #pragma unroll
        for (int nt = 0; nt < 4; nt++) {
            cm[nt][0] = cm[nt][0] * inv0 + 1e-6f;
            cm[nt][1] = cm[nt][1] * inv0 + 1e-6f;
            cm[nt][2] = cm[nt][2] * inv1 + 1e-6f;
            cm[nt][3] = cm[nt][3] * inv1 + 1e-6f;
        }

        // ---- column partial sums (warp's 16 rows) ----
        float cs0[4], cs1[4];
        #pragma unroll
        for (int nt = 0; nt < 4; nt++) {
            cs0[nt] = cm[nt][0] + cm[nt][2];
            cs1[nt] = cm[nt][1] + cm[nt][3];
        }
        #pragma unroll
        for (int o = 4; o < 32; o <<= 1) {
            #pragma unroll
            for (int nt = 0; nt < 4; nt++) {
                cs0[nt] += __shfl_xor_sync(0xffffffffu, cs0[nt], o);
                cs1[nt] += __shfl_xor_sync(0xffffffffu, cs1[nt], o);
            }
        }
        if ((lane >> 2) == 0) {
            #pragma unroll
            for (int nt = 0; nt < 4; nt++) {
                const int col = ct + nt * 8 + cb;
                cpart[rt][col]     = cs0[nt];
                cpart[rt][col + 1] = cs1[nt];
            }
        }
        __syncthreads();
        if (tid < 64)
            csum_inv[tid] = 1.0f / (cpart[0][tid] + cpart[1][tid] + cpart[2][tid] + cpart[3][tid]);
        __syncthreads();

        // ---- normalize + store straight from registers ----
        float* outb = out + (long)blockIdx.x * 4096;
        #pragma unroll
        for (int nt = 0; nt < 4; nt++) {
            const int col = ct + nt * 8 + cb;
            const float i0 = csum_inv[col], i1 = csum_inv[col + 1];
            *(float2*)&outb[r0 * 64 + col] =
                make_float2(cm[nt][0] * i0, cm[nt][1] * i1);
            *(float2*)&outb[(r0 + 8) * 64 + col] =
                make_float2(cm[nt][2] * i0, cm[nt][3] * i1);
        }
    }
}

extern "C" void kernel_launch(void* const* d_in, const int* in_sizes, int n_in,
                              void* d_out, int out_size) {
    const float* yhat = (const float*)d_in[0];
    const float* y    = (const float*)d_in[1];
    const float* kmat = (const float*)d_in[2];
    const float* qmat = (const float*)d_in[3];
    float* out = (float*)d_out;

    const int N = in_sizes[1] / HDIM;
    const int grid = N / 64;                 // 1 segment per CTA

    split_kq_kernel<<<128, 256>>>(kmat, qmat);

    cudaFuncSetAttribute(cross_att_r12,
                         cudaFuncAttributeMaxDynamicSharedMemorySize, (int)SMEM_BYTES);
    cross_att_r12<<<grid, 256, SMEM_BYTES>>>(yhat, y, out);
}

// round 13
// speedup vs baseline: 1.5740x; 1.5740x over previous
#include <cuda_runtime.h>
#include <cuda_fp16.h>
#include <cstdint>

// CrossAttUnit fused — fp16-split (Ootomo) warp MMA, hybrid R13:
// A through double-buffered smem stages (LDSM), B via direct per-lane
// fragment LDG (L1-resident image). One barrier per chunk. 4 CTAs/SM.
// N=262144, H=256, D=64, L=64, B=4096. 1 segment/CTA, 256 threads.

#define HDIM 256
#define SMEM_BYTES 32768u
// A stages: stage s at s*16384 (AY_HI +0, AY_LO +4096, AH_HI +8192, AH_LO +12288)
// GEMM2 tiles alias 0..32768: ykhi 0, yklo 8192, yqhi 16384, yqlo 24576

// B fragment images: [chunk 0..7][mat 0..1][nhalf 0..1][u 0..3][lane 0..31][uint4]
__device__ __align__(16) unsigned char g_bh[65536];
__device__ __align__(16) unsigned char g_bl[65536];

__global__ void split_kq_kernel(const float* __restrict__ kmat,
                                const float* __restrict__ qmat) {
    int gid = blockIdx.x * 256 + threadIdx.x;        // 32768 = 2 x 256 x 64
    int m = gid >> 14, kglob = (gid >> 6) & 255, n = gid & 63;
    float x = m ? qmat[kglob * 64 + n] : kmat[kglob * 64 + n];
    __half hi = __float2half_rn(x);
    __half lo = __float2half_rn(x - __half2float(hi));
    int chunk = kglob >> 5, kk = kglob & 31, ks = kk >> 4, kr = kk & 15;
    int breg = kr >> 3, hpos = kr & 1, l2 = (kr >> 1) & 3;
    int nhalf = n >> 5, nn = n & 31, n8 = nn >> 3, lhi = nn & 7;
    int lane = lhi * 4 + l2;
    int regidx = ks * 8 + n8 * 2 + breg;
    int u = regidx >> 2, j = regidx & 3;
    uint32_t hoff = (uint32_t)((((chunk * 4 + m * 2 + nhalf) * 4 + u) * 32 + lane) * 8
                               + j * 2 + hpos);
    ((__half*)g_bh)[hoff] = hi;
    ((__half*)g_bl)[hoff] = lo;
}

__device__ __forceinline__ uint32_t smem_u32(const void* p) {
    uint32_t a;
    asm("{ .reg .u64 t; cvta.to.shared.u64 t, %1; cvt.u32.u64 %0, t; }" : "=r"(a) : "l"(p));
    return a;
}
__device__ __forceinline__ void ldsm4(uint32_t r[4], uint32_t addr) {
    asm volatile("ldmatrix.sync.aligned.m8n8.x4.shared.b16 {%0,%1,%2,%3}, [%4];"
                 : "=r"(r[0]), "=r"(r[1]), "=r"(r[2]), "=r"(r[3]) : "r"(addr));
}
__device__ __forceinline__ void mma16816(float c[4], const uint32_t a[4],
                                         uint32_t b0, uint32_t b1) {
    asm("mma.sync.aligned.m16n8k16.row.col.f32.f16.f16.f32 "
        "{%0,%1,%2,%3},{%4,%5,%6,%7},{%8,%9},{%0,%1,%2,%3};"
        : "+f"(c[0]), "+f"(c[1]), "+f"(c[2]), "+f"(c[3])
        : "r"(a[0]), "r"(a[1]), "r"(a[2]), "r"(a[3]), "r"(b0), "r"(b1));
}
__device__ __forceinline__ void split2(float x0, float x1, uint32_t& hi, uint32_t& lo) {
    __half h0 = __float2half_rn(x0), h1 = __float2half_rn(x1);
    __half l0 = __float2half_rn(x0 - __half2float(h0));
    __half l1 = __float2half_rn(x1 - __half2float(h1));
    __half2 H = __halves2half2(h0, h1), L = __halves2half2(l0, l1);
    hi = *(uint32_t*)&H;
    lo = *(uint32_t*)&L;
}

__global__ __launch_bounds__(256, 4)
void cross_att_r13(const float* __restrict__ yhat,
                   const float* __restrict__ y,
                   float* __restrict__ out) {
    extern __shared__ unsigned char smc[];
    const uint32_t sb = smem_u32(smc);
    const int tid = threadIdx.x, wid = tid >> 5, lane = tid & 31;
    __shared__ float rred[2][64];
    __shared__ float rsum[2][64];
    __shared__ float cpart[4][64];
    __shared__ float csum_inv[64];

    const long rowbase = (long)blockIdx.x * 64;
    const int mat = wid >> 2;                // 0: yk (y,k) ; 1: yq (yhat,q)
    const int w2 = wid & 3;
    const int mrow0 = (w2 & 1) * 32;
    const int ncol0 = (w2 >> 1) * 32;

    float cc[2][4][4];
    #pragma unroll
    for (int a = 0; a < 2; a++)
        #pragma unroll
        for (int b = 0; b < 4; b++)
            #pragma unroll
            for (int j = 0; j < 4; j++) cc[a][b][j] = 0.0f;

    // ---- A LDSM bases (stage 0; stage 1 adds +16384) ----
    // A tiles: SW64, 64B rows. addr(row,g) = base + row*64 + ((g^((row>>1)&3))<<4)
    const uint32_t Abase = sb + (mat ? 8192u : 0u);
    const int rowA0 = mrow0 + (lane & 15), rowA1 = rowA0 + 16;
    const int gA = lane >> 4;
    const uint32_t aH0 = Abase + (uint32_t)(rowA0 * 64 + ((gA ^ ((rowA0 >> 1) & 3)) << 4));
    const uint32_t aH1 = Abase + (uint32_t)(rowA1 * 64 + ((gA ^ ((rowA1 >> 1) & 3)) << 4));
    // ks1: ^32 ; LO tile: +4096

    // ---- B fragment image pointers (per warp, per lane) ----
    const uint4* pbh = (const uint4*)g_bh + (uint32_t)((mat * 2 + (ncol0 >> 5)) * 128 + lane);
    const uint4* pbl = (const uint4*)g_bl + (uint32_t)((mat * 2 + (ncol0 >> 5)) * 128 + lane);

    // ---- A staging source/dest (stage 0; stage 1 adds +16384) ----
    const int sr = tid >> 3, sc4 = tid & 7;
    const uint32_t soA = (uint32_t)(sr * 64 + (((sc4 >> 1) ^ ((sr >> 1) & 3)) << 4) + (sc4 & 1) * 8);
    const int sr2 = sr + 32;
    const uint32_t soA2 = (uint32_t)(sr2 * 64 + (((sc4 >> 1) ^ ((sr2 >> 1) & 3)) << 4) + (sc4 & 1) * 8);

    // ---------------- GEMM1: 8 chunks of K=32, double-buffered A stage ----------------
    #pragma unroll 1
    for (int c = 0; c < 8; c++) {
        const uint32_t st = (uint32_t)((c & 1) * 16384);
        // A: 64 rows x 32 cols fp32 -> hi/lo fp16 into stage st
        #pragma unroll
        for (int t = 0; t < 2; t++) {
            const int row = t ? sr2 : sr;
            const uint32_t so = (t ? soA2 : soA) + st;
            const long g = (rowbase + row) * HDIM + c * 32 + sc4 * 4;
            float4 vy = *(const float4*)&y[g];
            float4 vh = *(const float4*)&yhat[g];
            uint2 yh, yl, hh, hl;
            split2(vy.x, vy.y, yh.x, yl.x); split2(vy.z, vy.w, yh.y, yl.y);
            split2(vh.x, vh.y, hh.x, hl.x); split2(vh.z, vh.w, hh.y, hl.y);
            *(uint2*)(smc + so)          = yh;   // AY_HI
            *(uint2*)(smc + 4096u + so)  = yl;   // AY_LO
            *(uint2*)(smc + 8192u + so)  = hh;   // AH_HI
            *(uint2*)(smc + 12288u + so) = hl;   // AH_LO
        }
        __syncthreads();

        #pragma unroll
        for (int ks = 0; ks < 2; ks++) {
            // B fragments via direct LDG (L1-resident image)
            const uint4 BH0 = pbh[c * 512 + ks * 64];
            const uint4 BH1 = pbh[c * 512 + ks * 64 + 32];
            const uint4 BL0 = pbl[c * 512 + ks * 64];
            const uint4 BL1 = pbl[c * 512 + ks * 64 + 32];

            const uint32_t kx = ks ? 32u : 0u;
            uint32_t ah0[4], al0[4], ah1[4], al1[4];
            ldsm4(ah0, (aH0 ^ kx) + st);
            ldsm4(al0, ((aH0 + 4096u) ^ kx) + st);
            ldsm4(ah1, (aH1 ^ kx) + st);
            ldsm4(al1, ((aH1 + 4096u) ^ kx) + st);

            // per-accumulator order: hh, hl, lh (matches prior rounds)
            mma16816(cc[0][0], ah0, BH0.x, BH0.y);
            mma16816(cc[0][1], ah0, BH0.z, BH0.w);
            mma16816(cc[0][2], ah0, BH1.x, BH1.y);
            mma16816(cc[0][3], ah0, BH1.z, BH1.w);
            mma16816(cc[1][0], ah1, BH0.x, BH0.y);
            mma16816(cc[1][1], ah1, BH0.z, BH0.w);
            mma16816(cc[1][2], ah1, BH1.x, BH1.y);
            mma16816(cc[1][3], ah1, BH1.z, BH1.w);
            mma16816(cc[0][0], ah0, BL0.x, BL0.y);
            mma16816(cc[0][1], ah0, BL0.z, BL0.w);
            mma16816(cc[0][2], ah0, BL1.x, BL1.y);
            mma16816(cc[0][3], ah0, BL1.z, BL1.w);
            mma16816(cc[1][0], ah1, BL0.x, BL0.y);
            mma16816(cc[1][1], ah1, BL0.z, BL0.w);
            mma16816(cc[1][2], ah1, BL1.x, BL1.y);
            mma16816(cc[1][3], ah1, BL1.z, BL1.w);
            mma16816(cc[0][0], al0, BH0.x, BH0.y);
            mma16816(cc[0][1], al0, BH0.z, BH0.w);
            mma16816(cc[0][2], al0, BH1.x, BH1.y);
            mma16816(cc[0][3], al0, BH1.z, BH1.w);
            mma16816(cc[1][0], al1, BH0.x, BH0.y);
            mma16816(cc[1][1], al1, BH0.z, BH0.w);
            mma16816(cc[1][2], al1, BH1.x, BH1.y);
            mma16816(cc[1][3], al1, BH1.z, BH1.w);
        }
    }
    __syncthreads();   // all stage reads done; GEMM2 tiles may overwrite

    // ---------------- split yk/yq -> GEMM2 tiles (SW128, 64x128B) ----------------
    {
        const uint32_t HIb = mat ? 16384u : 0u;     // yq hi : yk hi
        const int rbase = mrow0 + (lane >> 2);
        const int cbase = ncol0 + (lane & 3) * 2;
        #pragma unroll
        for (int mt = 0; mt < 2; mt++) {
            #pragma unroll
            for (int nt = 0; nt < 4; nt++) {
                const int col = cbase + nt * 8;
                const uint32_t cpartb = (uint32_t)(((col >> 3) << 4) + (col & 7) * 2);
                #pragma unroll
                for (int h = 0; h < 2; h++) {
                    const int r = rbase + mt * 16 + h * 8;
                    const uint32_t off = (uint32_t)(r * 128) + (cpartb ^ (uint32_t)((r & 7) << 4));
                    uint32_t hi, lo;
                    split2(cc[mt][nt][2 * h], cc[mt][nt][2 * h + 1], hi, lo);
                    *(uint32_t*)(smc + HIb + off)         = hi;
                    *(uint32_t*)(smc + HIb + 8192u + off) = lo;
                }
            }
        }
    }
    __syncthreads();

    // ---------------- GEMM2 + register epilogue ----------------
    {
        const int rt = wid & 3, ch = wid >> 2;
        const int ct = ch * 32;
        float cm[4][4];
        #pragma unroll
        for (int n = 0; n < 4; n++)
            #pragma unroll
            for (int j = 0; j < 4; j++) cm[n][j] = 0.0f;

        const int rowG = rt * 16 + (lane & 15);
        const int g0 = lane >> 4;
        const uint32_t aBase = sb + (uint32_t)(rowG * 128 + ((g0 ^ (rowG & 7)) << 4));
        const int rowB0 = ct + (lane & 15), rowB1 = rowB0 + 16;
        const uint32_t bBase0 = sb + 16384u + (uint32_t)(rowB0 * 128 + ((g0 ^ (rowB0 & 7)) << 4));
        const uint32_t bBase1 = sb + 16384u + (uint32_t)(rowB1 * 128 + ((g0 ^ (rowB1 & 7)) << 4));

        #pragma unroll
        for (int ks = 0; ks < 4; ks++) {
            const uint32_t kx = (uint32_t)(ks * 32);
            uint32_t Ah[4], Al[4];
            ldsm4(Ah, aBase ^ kx);
            ldsm4(Al, (aBase + 8192u) ^ kx);
            #pragma unroll
            for (int nl = 0; nl < 2; nl++) {
                const uint32_t bB = nl ? bBase1 : bBase0;
                uint32_t Bh[4], Bl[4];
                ldsm4(Bh, bB ^ kx);
                ldsm4(Bl, (bB + 8192u) ^ kx);
                const int nb = 2 * nl;
                mma16816(cm[nb],     Ah, Bh[0], Bh[2]);
                mma16816(cm[nb + 1], Ah, Bh[1], Bh[3]);
                mma16816(cm[nb],     Ah, Bl[0], Bl[2]);
                mma16816(cm[nb + 1], Ah, Bl[1], Bl[3]);
                mma16816(cm[nb],     Al, Bh[0], Bh[2]);
                mma16816(cm[nb + 1], Al, Bh[1], Bh[3]);
            }
        }

        // ---- scale ----
        #pragma unroll
        for (int nt = 0; nt < 4; nt++)
            #pragma unroll
            for (int j = 0; j < 4; j++) cm[nt][j] *= 0.125f;

        const int r0 = rt * 16 + (lane >> 2);
        const int cb = (lane & 3) * 2;

        // ---- row max over warp's 32 cols, then cross-warp merge ----
        float m0 = fmaxf(fmaxf(cm[0][0], cm[0][1]), fmaxf(cm[1][0], cm[1][1]));
        m0 = fmaxf(m0, fmaxf(fmaxf(cm[2][0], cm[2][1]), fmaxf(cm[3][0], cm[3][1])));
        float m1 = fmaxf(fmaxf(cm[0][2], cm[0][3]), fmaxf(cm[1][2], cm[1][3]));
        m1 = fmaxf(m1, fmaxf(fmaxf(cm[2][2], cm[2][3]), fmaxf(cm[3][2], cm[3][3])));
        m0 = fmaxf(m0, __shfl_xor_sync(0xffffffffu, m0, 1));
        m0 = fmaxf(m0, __shfl_xor_sync(0xffffffffu, m0, 2));
        m1 = fmaxf(m1, __shfl_xor_sync(0xffffffffu, m1, 1));
        m1 = fmaxf(m1, __shfl_xor_sync(0xffffffffu, m1, 2));
        if ((lane & 3) == 0) { rred[ch][r0] = m0; rred[ch][r0 + 8] = m1; }
        __syncthreads();
        m0 = fmaxf(m0, rred[ch ^ 1][r0]);
        m1 = fmaxf(m1, rred[ch ^ 1][r0 + 8]);

        // ---- exp + row sums ----
        float s0 = 0.0f, s1 = 0.0f;
        #pragma unroll
        for (int nt = 0; nt < 4; nt++) {
            cm[nt][0] = __expf(cm[nt][0] - m0); s0 += cm[nt][0];
            cm[nt][1] = __expf(cm[nt][1] - m0); s0 += cm[nt][1];
            cm[nt][2] = __expf(cm[nt][2] - m1); s1 += cm[nt][2];
            cm[nt][3] = __expf(cm[nt][3] - m1); s1 += cm[nt][3];
        }
        s0 += __shfl_xor_sync(0xffffffffu, s0, 1);
        s0 += __shfl_xor_sync(0xffffffffu, s0, 2);
        s1 += __shfl_xor_sync(0xffffffffu, s1, 1);
        s1 += __shfl_xor_sync(0xffffffffu, s1, 2);
        if ((lane & 3) == 0) { rsum[ch][r0] = s0; rsum[ch][r0 + 8] = s1; }
        __syncthreads();
        s0 += rsum[ch ^ 1][r0];
        s1 += rsum[ch ^ 1][r0 + 8];
        const float inv0 = 1.0f / s0, inv1 = 1.0f / s1;
        #pragma unroll
        for (int nt = 0; nt < 4; nt++) {
            cm[nt][0] = cm[nt][0] * inv0 + 1e-6f;
            cm[nt][1] = cm[nt][1] * inv0 + 1e-6f;
            cm[nt][2] = cm[nt][2] * inv1 + 1e-6f;
            cm[nt][3] = cm[nt][3] * inv1 + 1e-6f;
        }

        // ---- column partial sums (warp's 16 rows) ----
        float cs0[4], cs1[4];
        #pragma unroll
        for (int nt = 0; nt < 4; nt++) {
            cs0[nt] = cm[nt][0] + cm[nt][2];
            cs1[nt] = cm[nt][1] + cm[nt][3];
        }
        #pragma unroll
        for (int o = 4; o < 32; o <<= 1) {
            #pragma unroll
            for (int nt = 0; nt < 4; nt++) {
                cs0[nt] += __shfl_xor_sync(0xffffffffu, cs0[nt], o);
                cs1[nt] += __shfl_xor_sync(0xffffffffu, cs1[nt], o);
            }
        }
        if ((lane >> 2) == 0) {
            #pragma unroll
            for (int nt = 0; nt < 4; nt++) {
                const int col = ct + nt * 8 + cb;
                cpart[rt][col]     = cs0[nt];
                cpart[rt][col + 1] = cs1[nt];
            }
        }
        __syncthreads();
        if (tid < 64)
            csum_inv[tid] = 1.0f / (cpart[0][tid] + cpart[1][tid] + cpart[2][tid] + cpart[3][tid]);
        __syncthreads();

        // ---- normalize + store straight from registers ----
        float* outb = out + (long)blockIdx.x * 4096;
        #pragma unroll
        for (int nt = 0; nt < 4; nt++) {
            const int col = ct + nt * 8 + cb;
            const float i0 = csum_inv[col], i1 = csum_inv[col + 1];
            *(float2*)&outb[r0 * 64 + col] =
                make_float2(cm[nt][0] * i0, cm[nt][1] * i1);
            *(float2*)&outb[(r0 + 8) * 64 + col] =
                make_float2(cm[nt][2] * i0, cm[nt][3] * i1);
        }
    }
}

extern "C" void kernel_launch(void* const* d_in, const int* in_sizes, int n_in,
                              void* d_out, int out_size) {
    const float* yhat = (const float*)d_in[0];
    const float* y    = (const float*)d_in[1];
    const float* kmat = (const float*)d_in[2];
    const float* qmat = (const float*)d_in[3];
    float* out = (float*)d_out;

    const int N = in_sizes[1] / HDIM;
    const int grid = N / 64;                 // 1 segment per CTA

    split_kq_kernel<<<128, 256>>>(kmat, qmat);

    cudaFuncSetAttribute(cross_att_r13,
                         cudaFuncAttributeMaxDynamicSharedMemorySize, (int)SMEM_BYTES);
    cross_att_r13<<<grid, 256, SMEM_BYTES>>>(yhat, y, out);
}

// round 14
// speedup vs baseline: 2.0460x; 1.2999x over previous
#include <cuda_runtime.h>
#include <cuda_fp16.h>
#include <cstdint>

// CrossAttUnit fused — fp16-split (Ootomo) warp MMA, R14: fully pipelined GEMM1.
// A and B double-buffered in smem (64 KB), ONE barrier per chunk, cp.async B
// prefetch + half-chunk A register prefetch overlap the MMA phase. 3 CTAs/SM.
// N=262144, H=256, D=64, L=64, B=4096. 1 segment/CTA, 256 threads.

#define HDIM 256
#define SMEM_BYTES 65536u
// A stages: s*16384 (AY_HI +0, AY_LO +4096, AH_HI +8192, AH_LO +12288), SW64 tiles
// B stages: 32768 + s*16384 (Khi +0, Klo +4096, Qhi +8192, Qlo +12288), SW128 tiles
// GEMM2 tiles alias 0..32768: ykhi 0, yklo 8192, yqhi 16384, yqlo 24576

// pre-packed B image: [chunk 0..7][buf Khi,Klo,Qhi,Qlo][32 rows x 128 B, sw128]
__device__ __align__(16) unsigned char g_b[131072];

__global__ void split_kq_kernel(const float* __restrict__ kmat,
                                const float* __restrict__ qmat) {
    int gid = blockIdx.x * 256 + threadIdx.x;        // 32768 = 2 x 256 x 64
    int mat = gid >> 14, k = (gid >> 6) & 255, n = gid & 63;
    float x = mat ? qmat[k * 64 + n] : kmat[k * 64 + n];
    __half hi = __float2half_rn(x);
    __half lo = __float2half_rn(x - __half2float(hi));
    int c = k >> 5, kw = k & 31;
    uint32_t off = (uint32_t)(kw * 128 + (((n >> 3) ^ (kw & 7)) << 4) + (n & 7) * 2);
    uint32_t tb = (uint32_t)(c * 4 + mat * 2) * 4096u;
    *(__half*)&g_b[tb + off]         = hi;
    *(__half*)&g_b[tb + 4096u + off] = lo;
}

__device__ __forceinline__ uint32_t smem_u32(const void* p) {
    uint32_t a;
    asm("{ .reg .u64 t; cvta.to.shared.u64 t, %1; cvt.u32.u64 %0, t; }" : "=r"(a) : "l"(p));
    return a;
}
__device__ __forceinline__ void ldsm4(uint32_t r[4], uint32_t addr) {
    asm volatile("ldmatrix.sync.aligned.m8n8.x4.shared.b16 {%0,%1,%2,%3}, [%4];"
                 : "=r"(r[0]), "=r"(r[1]), "=r"(r[2]), "=r"(r[3]) : "r"(addr));
}
__device__ __forceinline__ void ldsm4t(uint32_t r[4], uint32_t addr) {
    asm volatile("ldmatrix.sync.aligned.m8n8.x4.trans.shared.b16 {%0,%1,%2,%3}, [%4];"
                 : "=r"(r[0]), "=r"(r[1]), "=r"(r[2]), "=r"(r[3]) : "r"(addr));
}
__device__ __forceinline__ void mma16816(float c[4], const uint32_t a[4],
                                         uint32_t b0, uint32_t b1) {
    asm("mma.sync.aligned.m16n8k16.row.col.f32.f16.f16.f32 "
        "{%0,%1,%2,%3},{%4,%5,%6,%7},{%8,%9},{%0,%1,%2,%3};"
        : "+f"(c[0]), "+f"(c[1]), "+f"(c[2]), "+f"(c[3])
        : "r"(a[0]), "r"(a[1]), "r"(a[2]), "r"(a[3]), "r"(b0), "r"(b1));
}
__device__ __forceinline__ void split2(float x0, float x1, uint32_t& hi, uint32_t& lo) {
    __half h0 = __float2half_rn(x0), h1 = __float2half_rn(x1);
    __half l0 = __float2half_rn(x0 - __half2float(h0));
    __half l1 = __float2half_rn(x1 - __half2float(h1));
    __half2 H = __halves2half2(h0, h1), L = __halves2half2(l0, l1);
    hi = *(uint32_t*)&H;
    lo = *(uint32_t*)&L;
}

#define CP_ASYNC16(saddr, gptr) \
    asm volatile("cp.async.cg.shared.global [%0], [%1], 16;" :: "r"(saddr), "l"(gptr) : "memory")
#define CP_COMMIT() asm volatile("cp.async.commit_group;" ::: "memory")
#define CP_WAIT0()  asm volatile("cp.async.wait_group 0;" ::: "memory")

__global__ __launch_bounds__(256, 3)
void cross_att_r14(const float* __restrict__ yhat,
                   const float* __restrict__ y,
                   float* __restrict__ out) {
    extern __shared__ unsigned char smc[];
    const uint32_t sb = smem_u32(smc);
    const int tid = threadIdx.x, wid = tid >> 5, lane = tid & 31;
    __shared__ float rred[2][64];
    __shared__ float rsum[2][64];
    __shared__ float cpart[4][64];
    __shared__ float csum_inv[64];

    const long rowbase = (long)blockIdx.x * 64;
    const int mat = wid >> 2;                // 0: yk (y,k) ; 1: yq (yhat,q)
    const int w2 = wid & 3;
    const int mrow0 = (w2 & 1) * 32;
    const int ncol0 = (w2 >> 1) * 32;
    const float* amat0 = mat ? yhat : y;     // unused marker; A staging covers both

    float cc[2][4][4];
    #pragma unroll
    for (int a = 0; a < 2; a++)
        #pragma unroll
        for (int b = 0; b < 4; b++)
            #pragma unroll
            for (int j = 0; j < 4; j++) cc[a][b][j] = 0.0f;
    (void)amat0;

    // ---- A LDSM bases (stage 0; stage 1 adds +16384) ----
    const uint32_t Abase = sb + (mat ? 8192u : 0u);
    const int rowA0 = mrow0 + (lane & 15), rowA1 = rowA0 + 16;
    const int gA = lane >> 4;
    const uint32_t aH0 = Abase + (uint32_t)(rowA0 * 64 + ((gA ^ ((rowA0 >> 1) & 3)) << 4));
    const uint32_t aH1 = Abase + (uint32_t)(rowA1 * 64 + ((gA ^ ((rowA1 >> 1) & 3)) << 4));
    // ks1: ^32 ; LO tile: +4096

    // ---- B LDSM base (stage 0 at sb+32768; stage 1 adds +16384) ----
    const uint32_t Bbase = sb + 32768u + (mat ? 8192u : 0u);
    const int kB = ((lane >> 3) & 1) * 8 + (lane & 7);
    const int gB = ((lane >> 4) & 1) + (ncol0 >> 3);   // logical granule incl. warp col block
    const uint32_t bH0 = Bbase + (uint32_t)(kB * 128 + ((gB ^ (kB & 7)) << 4));
    // nt1: ^32 ; ks1: +2048 ; LO: +4096

    // ---- A staging source/dest (stage 0; stage 1 adds +16384) ----
    const int sr = tid >> 3, sc4 = tid & 7;
    const uint32_t soA = (uint32_t)(sr * 64 + (((sc4 >> 1) ^ ((sr >> 1) & 3)) << 4) + (sc4 & 1) * 8);
    const int sr2 = sr + 32;
    const uint32_t soA2 = (uint32_t)(sr2 * 64 + (((sc4 >> 1) ^ ((sr2 >> 1) & 3)) << 4) + (sc4 & 1) * 8);

    // ---------------- prologue: B(0) cp.async ; A(0) staged to stage 0 ----------------
    {
        #pragma unroll
        for (int i = 0; i < 4; i++) {
            const uint32_t idx = (uint32_t)(i * 256 + tid);
            CP_ASYNC16(sb + 32768u + idx * 16u, (const char*)g_b + idx * 16);
        }
        CP_COMMIT();
        #pragma unroll
        for (int t = 0; t < 2; t++) {
            const int row = t ? sr2 : sr;
            const uint32_t so = t ? soA2 : soA;
            const long g = (rowbase + row) * HDIM + sc4 * 4;
            float4 vy = *(const float4*)&y[g];
            float4 vh = *(const float4*)&yhat[g];
            uint2 yh, yl, hh, hl;
            split2(vy.x, vy.y, yh.x, yl.x); split2(vy.z, vy.w, yh.y, yl.y);
            split2(vh.x, vh.y, hh.x, hl.x); split2(vh.z, vh.w, hh.y, hl.y);
            *(uint2*)(smc + so)          = yh;
            *(uint2*)(smc + 4096u + so)  = yl;
            *(uint2*)(smc + 8192u + so)  = hh;
            *(uint2*)(smc + 12288u + so) = hl;
        }
    }

    // ---------------- GEMM1: 8 chunks, ONE barrier per chunk ----------------
    #pragma unroll 1
    for (int c = 0; c < 8; c++) {
        CP_WAIT0();             // B(c) arrived
        __syncthreads();        // B(c)/A(c) visible; all prior-stage reads ordered

        const uint32_t st  = (uint32_t)((c & 1) << 14);        // current stage
        const uint32_t stn = (uint32_t)((~c & 1) << 14);       // next stage

        // issue B(c+1) into the other stage (overlaps MMA phase)
        if (c < 7) {
            const char* src = (const char*)g_b + (c + 1) * 16384;
            #pragma unroll
            for (int i = 0; i < 4; i++) {
                const uint32_t idx = (uint32_t)(i * 256 + tid);
                CP_ASYNC16(sb + 32768u + stn + idx * 16u, src + idx * 16);
            }
            CP_COMMIT();
        }

        // prefetch half of A(c+1) (rows sr) — latency hidden by MMA phase
        float4 pvy, pvh;
        if (c < 7) {
            const long g = (rowbase + sr) * HDIM + (c + 1) * 32 + sc4 * 4;
            pvy = *(const float4*)&y[g];
            pvh = *(const float4*)&yhat[g];
        }

        // ---- MMA phase ----
        #pragma unroll
        for (int ks = 0; ks < 2; ks++) {
            const uint32_t kx = ks ? 32u : 0u, dk = ks ? 2048u : 0u;
            uint32_t ah0[4], al0[4], ah1[4], al1[4];
            ldsm4(ah0, (aH0 ^ kx) + st);
            ldsm4(al0, ((aH0 + 4096u) ^ kx) + st);
            ldsm4(ah1, (aH1 ^ kx) + st);
            ldsm4(al1, ((aH1 + 4096u) ^ kx) + st);
            #pragma unroll
            for (int nt = 0; nt < 2; nt++) {
                const uint32_t nx = nt ? 32u : 0u;
                uint32_t bh[4], bl[4];
                ldsm4t(bh, ((bH0 + dk) ^ nx) + st);
                ldsm4t(bl, ((bH0 + 4096u + dk) ^ nx) + st);
                const int nb = 2 * nt;
                // per-accumulator order: hh, hl, lh (matches prior rounds)
                mma16816(cc[0][nb],     ah0, bh[0], bh[1]);
                mma16816(cc[0][nb + 1], ah0, bh[2], bh[3]);
                mma16816(cc[1][nb],     ah1, bh[0], bh[1]);
                mma16816(cc[1][nb + 1], ah1, bh[2], bh[3]);
                mma16816(cc[0][nb],     ah0, bl[0], bl[1]);
                mma16816(cc[0][nb + 1], ah0, bl[2], bl[3]);
                mma16816(cc[1][nb],     ah1, bl[0], bl[1]);
                mma16816(cc[1][nb + 1], ah1, bl[2], bl[3]);
                mma16816(cc[0][nb],     al0, bh[0], bh[1]);
                mma16816(cc[0][nb + 1], al0, bh[2], bh[3]);
                mma16816(cc[1][nb],     al1, bh[0], bh[1]);
                mma16816(cc[1][nb + 1], al1, bh[2], bh[3]);
            }
        }

        // ---- stage A(c+1) into next stage (no barrier needed: last read iter c-1) ----
        if (c < 7) {
            {
                uint2 yh, yl, hh, hl;
                split2(pvy.x, pvy.y, yh.x, yl.x); split2(pvy.z, pvy.w, yh.y, yl.y);
                split2(pvh.x, pvh.y, hh.x, hl.x); split2(pvh.z, pvh.w, hh.y, hl.y);
                const uint32_t so = soA + stn;
                *(uint2*)(smc + so)          = yh;
                *(uint2*)(smc + 4096u + so)  = yl;
                *(uint2*)(smc + 8192u + so)  = hh;
                *(uint2*)(smc + 12288u + so) = hl;
            }
            {
                const long g = (rowbase + sr2) * HDIM + (c + 1) * 32 + sc4 * 4;
                float4 vy = *(const float4*)&y[g];
                float4 vh = *(const float4*)&yhat[g];
                uint2 yh, yl, hh, hl;
                split2(vy.x, vy.y, yh.x, yl.x); split2(vy.z, vy.w, yh.y, yl.y);
                split2(vh.x, vh.y, hh.x, hl.x); split2(vh.z, vh.w, hh.y, hl.y);
                const uint32_t so = soA2 + stn;
                *(uint2*)(smc + so)          = yh;
                *(uint2*)(smc + 4096u + so)  = yl;
                *(uint2*)(smc + 8192u + so)  = hh;
                *(uint2*)(smc + 12288u + so) = hl;
            }
        }
    }
    __syncthreads();   // all GEMM1 reads done; GEMM2 tiles may overwrite A stages

    // ---------------- split yk/yq -> GEMM2 tiles (SW128, 64x128B) ----------------
    {
        const uint32_t HIb = mat ? 16384u : 0u;     // yq hi : yk hi
        const int rbase = mrow0 + (lane >> 2);
        const int cbase = ncol0 + (lane & 3) * 2;
        #pragma unroll
        for (int mt = 0; mt < 2; mt++) {
            #pragma unroll
            for (int nt = 0; nt < 4; nt++) {
                const int col = cbase + nt * 8;
                const uint32_t cpartb = (uint32_t)(((col >> 3) << 4) + (col & 7) * 2);
                #pragma unroll
                for (int h = 0; h < 2; h++) {
                    const int r = rbase + mt * 16 + h * 8;
                    const uint32_t off = (uint32_t)(r * 128) + (cpartb ^ (uint32_t)((r & 7) << 4));
                    uint32_t hi, lo;
                    split2(cc[mt][nt][2 * h], cc[mt][nt][2 * h + 1], hi, lo);
                    *(uint32_t*)(smc + HIb + off)         = hi;
                    *(uint32_t*)(smc + HIb + 8192u + off) = lo;
                }
            }
        }
    }
    __syncthreads();

    // ---------------- GEMM2 + register epilogue ----------------
    {
        const int rt = wid & 3, ch = wid >> 2;
        const int ct = ch * 32;
        float cm[4][4];
        #pragma unroll
        for (int n = 0; n < 4; n++)
            #pragma unroll
            for (int j = 0; j < 4; j++) cm[n][j] = 0.0f;

        const int rowG = rt * 16 + (lane & 15);
        const int g0 = lane >> 4;
        const uint32_t aBase = sb + (uint32_t)(rowG * 128 + ((g0 ^ (rowG & 7)) << 4));
        const int rowB0 = ct + (lane & 15), rowB1 = rowB0 + 16;
        const uint32_t bBase0 = sb + 16384u + (uint32_t)(rowB0 * 128 + ((g0 ^ (rowB0 & 7)) << 4));
        const uint32_t bBase1 = sb + 16384u + (uint32_t)(rowB1 * 128 + ((g0 ^ (rowB1 & 7)) << 4));

        #pragma unroll
        for (int ks = 0; ks < 4; ks++) {
            const uint32_t kx = (uint32_t)(ks * 32);
            uint32_t Ah[4], Al[4];
            ldsm4(Ah, aBase ^ kx);
            ldsm4(Al, (aBase + 8192u) ^ kx);
            #pragma unroll
            for (int nl = 0; nl < 2; nl++) {
                const uint32_t bB = nl ? bBase1 : bBase0;
                uint32_t Bh[4], Bl[4];
                ldsm4(Bh, bB ^ kx);
                ldsm4(Bl, (bB + 8192u) ^ kx);
                const int nb = 2 * nl;
                mma16816(cm[nb],     Ah, Bh[0], Bh[2]);
                mma16816(cm[nb + 1], Ah, Bh[1], Bh[3]);
                mma16816(cm[nb],     Ah, Bl[0], Bl[2]);
                mma16816(cm[nb + 1], Ah, Bl[1], Bl[3]);
                mma16816(cm[nb],     Al, Bh[0], Bh[2]);
                mma16816(cm[nb + 1], Al, Bh[1], Bh[3]);
            }
        }

        #pragma unroll
        for (int nt = 0; nt < 4; nt++)
            #pragma unroll
            for (int j = 0; j < 4; j++) cm[nt][j] *= 0.125f;

        const int r0 = rt * 16 + (lane >> 2);
        const int cb = (lane & 3) * 2;

        float m0 = fmaxf(fmaxf(cm[0][0], cm[0][1]), fmaxf(cm[1][0], cm[1][1]));
        m0 = fmaxf(m0, fmaxf(fmaxf(cm[2][0], cm[2][1]), fmaxf(cm[3][0], cm[3][1])));
        float m1 = fmaxf(fmaxf(cm[0][2], cm[0][3]), fmaxf(cm[1][2], cm[1][3]));
        m1 = fmaxf(m1, fmaxf(fmaxf(cm[2][2], cm[2][3]), fmaxf(cm[3][2], cm[3][3])));
        m0 = fmaxf(m0, __shfl_xor_sync(0xffffffffu, m0, 1));
        m0 = fmaxf(m0, __shfl_xor_sync(0xffffffffu, m0, 2));
        m1 = fmaxf(m1, __shfl_xor_sync(0xffffffffu, m1, 1));
        m1 = fmaxf(m1, __shfl_xor_sync(0xffffffffu, m1, 2));
        if ((lane & 3) == 0) { rred[ch][r0] = m0; rred[ch][r0 + 8] = m1; }
        __syncthreads();
        m0 = fmaxf(m0, rred[ch ^ 1][r0]);
        m1 = fmaxf(m1, rred[ch ^ 1][r0 + 8]);

        float s0 = 0.0f, s1 = 0.0f;
        #pragma unroll
        for (int nt = 0; nt < 4; nt++) {
            cm[nt][0] = __expf(cm[nt][0] - m0); s0 += cm[nt][0];
            cm[nt][1] = __expf(cm[nt][1] - m0); s0 += cm[nt][1];
            cm[nt][2] = __expf(cm[nt][2] - m1); s1 += cm[nt][2];
            cm[nt][3] = __expf(cm[nt][3] - m1); s1 += cm[nt][3];
        }
        s0 += __shfl_xor_sync(0xffffffffu, s0, 1);
        s0 += __shfl_xor_sync(0xffffffffu, s0, 2);
        s1 += __shfl_xor_sync(0xffffffffu, s1, 1);
        s1 += __shfl_xor_sync(0xffffffffu, s1, 2);
        if ((lane & 3) == 0) { rsum[ch][r0] = s0; rsum[ch][r0 + 8] = s1; }
        __syncthreads();
        s0 += rsum[ch ^ 1][r0];
        s1 += rsum[ch ^ 1][r0 + 8];
        const float inv0 = 1.0f / s0, inv1 = 1.0f / s1;
        #pragma unroll
        for (int nt = 0; nt < 4; nt++) {
            cm[nt][0] = cm[nt][0] * inv0 + 1e-6f;
            cm[nt][1] = cm[nt][1] * inv0 + 1e-6f;
            cm[nt][2] = cm[nt][2] * inv1 + 1e-6f;
            cm[nt][3] = cm[nt][3] * inv1 + 1e-6f;
        }

        float cs0[4], cs1[4];
        #pragma unroll
        for (int nt = 0; nt < 4; nt++) {
            cs0[nt] = cm[nt][0] + cm[nt][2];
            cs1[nt] = cm[nt][1] + cm[nt][3];
        }
        #pragma unroll
        for (int o = 4; o < 32; o <<= 1) {
            #pragma unroll
            for (int nt = 0; nt < 4; nt++) {
                cs0[nt] += __shfl_xor_sync(0xffffffffu, cs0[nt], o);
                cs1[nt] += __shfl_xor_sync(0xffffffffu, cs1[nt], o);
            }
        }
        if ((lane >> 2) == 0) {
            #pragma unroll
            for (int nt = 0; nt < 4; nt++) {
                const int col = ct + nt * 8 + cb;
                cpart[rt][col]     = cs0[nt];
                cpart[rt][col + 1] = cs1[nt];
            }
        }
        __syncthreads();
        if (tid < 64)
            csum_inv[tid] = 1.0f / (cpart[0][tid] + cpart[1][tid] + cpart[2][tid] + cpart[3][tid]);
        __syncthreads();

        float* outb = out + (long)blockIdx.x * 4096;
        #pragma unroll
        for (int nt = 0; nt < 4; nt++) {
            const int col = ct + nt * 8 + cb;
            const float i0 = csum_inv[col], i1 = csum_inv[col + 1];
            *(float2*)&outb[r0 * 64 + col] =
                make_float2(cm[nt][0] * i0, cm[nt][1] * i1);
            *(float2*)&outb[(r0 + 8) * 64 + col] =
                make_float2(cm[nt][2] * i0, cm[nt][3] * i1);
        }
    }
}

extern "C" void kernel_launch(void* const* d_in, const int* in_sizes, int n_in,
                              void* d_out, int out_size) {
    const float* yhat = (const float*)d_in[0];
    const float* y    = (const float*)d_in[1];
    const float* kmat = (const float*)d_in[2];
    const float* qmat = (const float*)d_in[3];
    float* out = (float*)d_out;

    const int N = in_sizes[1] / HDIM;
    const int grid = N / 64;                 // 1 segment per CTA

    split_kq_kernel<<<128, 256>>>(kmat, qmat);

    cudaFuncSetAttribute(cross_att_r14,
                         cudaFuncAttributeMaxDynamicSharedMemorySize, (int)SMEM_BYTES);
    cudaFuncSetAttribute(cross_att_r14,
                         cudaFuncAttributePreferredSharedMemoryCarveout, 100);
    cross_att_r14<<<grid, 256, SMEM_BYTES>>>(yhat, y, out);
}